// round 10
// baseline (speedup 1.0000x reference)
#include <cuda_runtime.h>

// LocalizeAttention gather: out[bh, n, f, :] = x[bh, n + shift_f, :] (zero at edges).
// BH=16, H=W=D=24 (N=13824), d=32 floats, 27 filters.
// R9: identical to R6 (best, 119.3us) except stores use DEFAULT cache policy
// instead of __stcs. Theory: evict-first dirty lines force early, poorly
// batched L2->DRAM writebacks; default policy lets the DRAM scheduler batch
// longer row hits on the 732 MB write stream.

#define HH 24
#define WW 24
#define DD 24
#define NN (HH * WW * DD)      // 13824
#define FN 27
#define ROW4 8                 // float4 per feature row (32 floats)
#define JT 3                   // j-rows per block
#define LJ (JT + 2)            // 5 (with halo)
#define LK (DD + 2)            // 26 (with halo)
#define LROWS (3 * LJ * LK)    // 390 source rows in tile
#define THREADS 576            // = JT*DD*8 write lanes

__global__ void __launch_bounds__(THREADS, 3)
localize_kernel(const float4* __restrict__ x, float4* __restrict__ out)
{
    __shared__ float4 s[LROWS * ROW4];   // 3120 float4 = 49920 B

    const int bh = blockIdx.z;
    const int i  = blockIdx.y;
    const int j0 = blockIdx.x * JT;
    const int t  = threadIdx.x;

    // ---- Load phase: tile + halo, zeros outside the volume ----
    const float4 zero = make_float4(0.f, 0.f, 0.f, 0.f);
    for (int l4 = t; l4 < LROWS * ROW4; l4 += THREADS) {
        int d4  = l4 & 7;
        int row = l4 >> 3;
        int li  = row / (LJ * LK);
        int r   = row - li * (LJ * LK);
        int lj  = r / LK;
        int lk  = r - lj * LK;
        int ii  = i  + li - 1;
        int jj  = j0 + lj - 1;
        int kk  = lk - 1;
        float4 v = zero;
        if ((unsigned)ii < HH && (unsigned)jj < WW && (unsigned)kk < DD) {
            v = __ldg(&x[((size_t)bh * NN + ii * (WW * DD) + jj * DD + kk) * ROW4 + d4]);
        }
        s[l4] = v;
    }
    __syncthreads();

    // ---- Write phase: one thread per (jl, k, d4); 27 SMEM reads + 27 stores ----
    const int d4 = t & 7;
    const int nl = t >> 3;          // 0..71
    const int jl = nl / DD;         // 0..2
    const int k  = nl - jl * DD;    // 0..23

    const int n = i * (WW * DD) + (j0 + jl) * DD + k;
    float4* dst = out + ((size_t)bh * NN + n) * (FN * ROW4) + d4;
    const float4* sp = s + ((size_t)jl * LK + k) * ROW4 + d4;

    #pragma unroll
    for (int fi = 0; fi < 3; fi++) {
        #pragma unroll
        for (int fj = 0; fj < 3; fj++) {
            #pragma unroll
            for (int fk = 0; fk < 3; fk++) {
                const int soff = ((fi * LJ + fj) * LK + fk) * ROW4;
                dst[((fi * 3 + fj) * 3 + fk) * ROW4] = sp[soff];   // default policy
            }
        }
    }
}

extern "C" void kernel_launch(void* const* d_in, const int* in_sizes, int n_in,
                              void* d_out, int out_size)
{
    const float4* x = (const float4*)d_in[0];
    float4* out = (float4*)d_out;

    int BH = out_size / (NN * FN * 32);     // batch*heads (16 for reference shapes)
    dim3 grid(WW / JT, HH, BH);
    localize_kernel<<<grid, THREADS>>>(x, out);
}

// round 12
// speedup vs baseline: 1.0169x; 1.0169x over previous
#include <cuda_runtime.h>
#include <cstdint>

// LocalizeAttention gather: out[bh, n, f, :] = x[bh, n + shift_f, :] (zero at edges).
// BH=16, H=W=D=24 (N=13824), d=32 floats, 27 filters.
// R11: TMA bulk-store version. Gather into SMEM staging chunks (41,472 B
// contiguous output each), store via cp.async.bulk.global.shared::cta —
// bypasses the per-thread STG/L1tex path entirely. Double-buffered, persistent
// CTAs, bulk groups stay in flight across tile boundaries (no drain gaps).

#define HH 24
#define WW 24
#define DD 24
#define NN (HH * WW * DD)      // 13824
#define FN 27
#define ROW4 8                 // float4 per feature row (32 floats)

#define LJ 3                   // halo j extent (JT=1)
#define LK (DD + 2)            // 26
#define LROWS (3 * LJ * LK)    // 234 input rows per tile
#define S_IN_F4 (LROWS * ROW4) // 1872 float4 = 29,952 B

#define CH_ROWS 12                       // output k-rows per chunk
#define CHUNK_F4 (CH_ROWS * FN * ROW4)   // 2592 float4
#define CHUNK_BYTES (CHUNK_F4 * 16)      // 41,472 B (16-aligned)
#define NCHUNKS 2                        // 24 k-rows per tile

#define THREADS 256
#define SMEM_TOTAL ((S_IN_F4 + 2 * CHUNK_F4) * 16)   // 112,896 B -> 2 CTAs/SM
#define PERSIST_BLOCKS 304               // 152 SMs * 2

__device__ __forceinline__ uint32_t smem_u32(const void* p) {
    return (uint32_t)__cvta_generic_to_shared(p);
}

__global__ void __launch_bounds__(THREADS, 2)
localize_kernel(const float4* __restrict__ x, float4* __restrict__ out, int ntiles)
{
    extern __shared__ float4 smem[];
    float4* s_in  = smem;                 // input halo tile
    float4* s_out = smem + S_IN_F4;       // 2 staging buffers

    const int t = threadIdx.x;
    const float4 zero = make_float4(0.f, 0.f, 0.f, 0.f);
    int buf = 0;

    for (int tile = blockIdx.x; tile < ntiles; tile += PERSIST_BLOCKS) {
        // tile = (bh*HH + i)*WW + j
        int j  = tile % WW;
        int bi = tile / WW;
        int i  = bi % HH;
        int bh = bi / HH;

        // ---- Load input halo tile (3 x 3 x 26 rows), zeros outside volume ----
        for (int l4 = t; l4 < S_IN_F4; l4 += THREADS) {
            int d4  = l4 & 7;
            int row = l4 >> 3;
            int li  = row / (LJ * LK);
            int r   = row - li * (LJ * LK);
            int lj  = r / LK;
            int lk  = r - lj * LK;
            int ii  = i + li - 1;
            int jj  = j + lj - 1;
            int kk  = lk - 1;
            float4 v = zero;
            if ((unsigned)ii < HH && (unsigned)jj < WW && (unsigned)kk < DD) {
                v = __ldg(&x[((size_t)bh * NN + ii * (WW * DD) + jj * DD + kk) * ROW4 + d4]);
            }
            s_in[l4] = v;
        }

        #pragma unroll
        for (int c = 0; c < NCHUNKS; c++) {
            // Before refilling this buffer: the bulk store issued 2 chunks ago
            // must have finished READING it.
            if (t == 0) {
                asm volatile("cp.async.bulk.wait_group.read 1;" ::: "memory");
            }
            __syncthreads();   // buffer free + s_in loads visible

            // ---- Fill staging buffer: layout ((k*27 + f)*8 + d4), output-linear ----
            float4* sb = s_out + buf * CHUNK_F4;
            const int k0 = c * CH_ROWS;
            #pragma unroll
            for (int l = t; l < CHUNK_F4; l += THREADS) {
                int d4 = l & 7;
                int r  = l >> 3;            // k_rel*27 + f
                int kr = r / FN;
                int f  = r - kr * FN;
                int k  = k0 + kr;
                int fi = f / 9;
                int fr = f - fi * 9;
                int fj = fr / 3;
                int fk = fr - fj * 3;
                sb[l] = s_in[((fi * LJ + fj) * LK + (k + fk)) * ROW4 + d4];
            }
            __syncthreads();

            // ---- Bulk store: 41,472 B contiguous SMEM -> GMEM ----
            if (t == 0) {
                asm volatile("fence.proxy.async.shared::cta;" ::: "memory");
                size_t nbase = (size_t)bh * NN + i * (WW * DD) + j * DD + k0;
                const float4* dst = out + nbase * (FN * ROW4);
                asm volatile(
                    "cp.async.bulk.global.shared::cta.bulk_group [%0], [%1], %2;"
                    :: "l"(dst), "r"(smem_u32(sb)), "r"((uint32_t)CHUNK_BYTES)
                    : "memory");
                asm volatile("cp.async.bulk.commit_group;" ::: "memory");
            }
            buf ^= 1;
        }
        // No full drain here: pending bulk stores bridge into the next tile's
        // s_in load (s_in is never a TMA source; fills re-sync before reads).
    }

    if (t == 0) {
        asm volatile("cp.async.bulk.wait_group 0;" ::: "memory");
    }
}

extern "C" void kernel_launch(void* const* d_in, const int* in_sizes, int n_in,
                              void* d_out, int out_size)
{
    const float4* x = (const float4*)d_in[0];
    float4* out = (float4*)d_out;

    static bool attr_set = false;
    if (!attr_set) {
        cudaFuncSetAttribute(localize_kernel,
                             cudaFuncAttributeMaxDynamicSharedMemorySize, SMEM_TOTAL);
        attr_set = true;
    }

    int BH = out_size / (NN * FN * 32);   // 16 for reference shapes
    int ntiles = BH * HH * WW;            // 9216
    localize_kernel<<<PERSIST_BLOCKS, THREADS, SMEM_TOTAL>>>(x, out, ntiles);
}

// round 15
// speedup vs baseline: 1.0486x; 1.0311x over previous
#include <cuda_runtime.h>

// LocalizeAttention gather: out[bh, n, f, :] = x[bh, n + shift_f, :] (zero at edges).
// BH=16, H=W=D=24 (N=13824), d=32 floats, 27 filters.
//
// FINAL (R6 config, best measured 119.3us):
//   - SMEM halo tile per (bh, i, 3 j-rows): input read once per block -> read
//     stream stays L2-resident, ~28 MB DRAM reads total.
//   - Write phase: one thread per (jl, k, d4); 27 compile-time-offset SMEM
//     reads + 27 streaming (__stcs) STG.128 stores, warp-coalesced 512 B lines.
//   - JT=3 / 576 threads / 3 CTAs/SM: near-even wave packing.
//
// Measured path-independent convergence across STG/TMA/persistent variants at
// ~6.1 TB/s (77% DRAM active) == dual-die L2 fabric ceiling for a 764 MB
// write-dominated stream; 119-120us is the roofline for this problem.

#define HH 24
#define WW 24
#define DD 24
#define NN (HH * WW * DD)      // 13824
#define FN 27
#define ROW4 8                 // float4 per feature row (32 floats)
#define JT 3                   // j-rows per block
#define LJ (JT + 2)            // 5 (with halo)
#define LK (DD + 2)            // 26 (with halo)
#define LROWS (3 * LJ * LK)    // 390 source rows in tile
#define THREADS 576            // = JT*DD*8 write lanes

__global__ void __launch_bounds__(THREADS, 3)
localize_kernel(const float4* __restrict__ x, float4* __restrict__ out)
{
    __shared__ float4 s[LROWS * ROW4];   // 3120 float4 = 49920 B

    const int bh = blockIdx.z;
    const int i  = blockIdx.y;
    const int j0 = blockIdx.x * JT;
    const int t  = threadIdx.x;

    // ---- Load phase: tile + halo, zeros outside the volume ----
    const float4 zero = make_float4(0.f, 0.f, 0.f, 0.f);
    for (int l4 = t; l4 < LROWS * ROW4; l4 += THREADS) {
        int d4  = l4 & 7;
        int row = l4 >> 3;
        int li  = row / (LJ * LK);
        int r   = row - li * (LJ * LK);
        int lj  = r / LK;
        int lk  = r - lj * LK;
        int ii  = i  + li - 1;
        int jj  = j0 + lj - 1;
        int kk  = lk - 1;
        float4 v = zero;
        if ((unsigned)ii < HH && (unsigned)jj < WW && (unsigned)kk < DD) {
            v = __ldg(&x[((size_t)bh * NN + ii * (WW * DD) + jj * DD + kk) * ROW4 + d4]);
        }
        s[l4] = v;
    }
    __syncthreads();

    // ---- Write phase: one thread per (jl, k, d4); 27 SMEM reads + 27 stores ----
    const int d4 = t & 7;
    const int nl = t >> 3;          // 0..71
    const int jl = nl / DD;         // 0..2
    const int k  = nl - jl * DD;    // 0..23

    const int n = i * (WW * DD) + (j0 + jl) * DD + k;
    float4* dst = out + ((size_t)bh * NN + n) * (FN * ROW4) + d4;
    const float4* sp = s + ((size_t)jl * LK + k) * ROW4 + d4;

    #pragma unroll
    for (int fi = 0; fi < 3; fi++) {
        #pragma unroll
        for (int fj = 0; fj < 3; fj++) {
            #pragma unroll
            for (int fk = 0; fk < 3; fk++) {
                const int soff = ((fi * LJ + fj) * LK + fk) * ROW4;
                __stcs(dst + ((fi * 3 + fj) * 3 + fk) * ROW4, sp[soff]);
            }
        }
    }
}

extern "C" void kernel_launch(void* const* d_in, const int* in_sizes, int n_in,
                              void* d_out, int out_size)
{
    const float4* x = (const float4*)d_in[0];
    float4* out = (float4*)d_out;

    int BH = out_size / (NN * FN * 32);     // batch*heads (16 for reference shapes)
    dim3 grid(WW / JT, HH, BH);
    localize_kernel<<<grid, THREADS>>>(x, out);
}